// round 16
// baseline (speedup 1.0000x reference)
#include <cuda_runtime.h>
#include <cuda_bf16.h>
#include <math.h>
#include <stdint.h>

#define NN  50000
#define EE  800000
#define FIN 64
#define HH  200
#define GG  256

#define LDK_BIG 640   // 3*200 padded to /64
#define LDK_S   192   // 3*64
#define GEMM_GRID 152 // persistent CTAs (GB300: 152 SMs)
#define PROP_CTAS (152 * 6)   // co-resident grid for fused prop (occ 6 guaranteed)
#define PRE_CTAS  (152 * 6)   // co-resident grid for fused preprocessing
#define PRE_CH    ((NN + PRE_CTAS - 1) / PRE_CTAS)   // 55 nodes per block chunk

// ------------------------- scratch (device globals; no allocation) ---------
__device__ __align__(256) float g_T[2][(size_t)NN * 600];   // ping-pong fp32 [N][3F]
__device__ __align__(256) __nv_bfloat16 g_AH[2][(size_t)NN * LDK_BIG];
__device__ __align__(256) __nv_bfloat16 g_AL[2][(size_t)NN * LDK_BIG];
__device__ __align__(256) __nv_bfloat16 g_B4h[4][256 * LDK_BIG];
__device__ __align__(256) __nv_bfloat16 g_B4l[4][256 * LDK_BIG];
__device__ int   g_src[EE], g_dstv[EE];
__device__ int2  g_cw[EE];                 // packed (col, weight-bits) CSR payload
__device__ int   g_deg[NN], g_indeg[NN], g_cursor[NN], g_batch[NN];
__device__ float g_dis[NN], g_diag[NN];
__device__ int   g_rowptr[NN + 1];
__device__ int   g_bsum[PRE_CTAS];
__device__ int   g_barcnt = 0, g_barphase = 0;
__device__ int   g_is64;

__device__ __forceinline__ uint32_t smem_to_u32(const void* p) {
    uint32_t a;
    asm("{ .reg .u64 t; cvta.to.shared.u64 t, %1; cvt.u32.u64 %0, t; }" : "=r"(a) : "l"(p));
    return a;
}

// sense-reversing grid barrier (all CTAs must be co-resident)
__device__ __forceinline__ void grid_barrier(int nb) {
    __threadfence();
    __syncthreads();
    if (threadIdx.x == 0) {
        int ph = *((volatile int*)&g_barphase);
        int t = atomicAdd(&g_barcnt, 1);
        if (t == nb - 1) {
            g_barcnt = 0;
            __threadfence();
            *((volatile int*)&g_barphase) = ph ^ 1;
        } else {
            while (*((volatile int*)&g_barphase) == ph) { }
        }
    }
    __syncthreads();
}

// ---------------- fused preprocessing (one persistent kernel) ---------------
// P0 zero counters + dtype detect | P1 convert edges/batch/x + degree atomics
// + AH1/AL1 pad zero | P2 node consts + per-block scan | P3 scan offsets |
// P4 CSR fill with inline edge weights
__global__ __launch_bounds__(256, 6) void k_preproc(
        const void* ei, const void* b, const float* __restrict__ x,
        const float* __restrict__ lmax) {
    const int stride = PRE_CTAS * 256;
    const int t0 = blockIdx.x * 256 + threadIdx.x;
    const int tid = threadIdx.x;

    // ---- P0: zero counters; detect dtype ----
    for (int i = t0; i < NN; i += stride) { g_deg[i] = 0; g_indeg[i] = 0; g_cursor[i] = 0; }
    if (t0 == 0) {
        const unsigned* u = (const unsigned*)ei;
        int z = 0;
        for (int j = 0; j < 32; j++)
            if (u[2 * j + 1] == 0u) z++;
        g_is64 = (z >= 16) ? 1 : 0;
    }
    grid_barrier(PRE_CTAS);

    // ---- P1: conversions + degree atomics + x copy + AH1/AL1 pad zero ----
    int is64 = *((volatile int*)&g_is64);
    if (is64) {
        const long long* p = (const long long*)ei;
        for (int e = t0; e < EE; e += stride) {
            int s = (int)p[e], d = (int)p[EE + e];
            g_src[e] = s; g_dstv[e] = d;
            atomicAdd(&g_deg[s], 1);
            atomicAdd(&g_indeg[d], 1);
        }
        const long long* pb = (const long long*)b;
        for (int n = t0; n < NN; n += stride) g_batch[n] = (int)pb[n];
    } else {
        const int* p = (const int*)ei;
        for (int e = t0; e < EE; e += stride) {
            int s = p[e], d = p[EE + e];
            g_src[e] = s; g_dstv[e] = d;
            atomicAdd(&g_deg[s], 1);
            atomicAdd(&g_indeg[d], 1);
        }
        const int* pb = (const int*)b;
        for (int n = t0; n < NN; n += stride) g_batch[n] = pb[n];
    }
    for (int i = t0; i < NN * FIN; i += stride) {
        int n = i >> 6, f = i & 63;
        float v = x[i];
        g_T[0][(size_t)n * 192 + f] = v;
        __nv_bfloat16 h = __float2bfloat16(v);
        size_t o = (size_t)n * LDK_S + f;
        g_AH[0][o] = h;
        g_AL[0][o] = __float2bfloat16(v - __bfloat162float(h));
    }
    // zero K-pad cols [600,640) of A-buffer 1 (untouched until layer-1 epilogue,
    // which writes only cols<200; props write 200-599 — pads stay disjoint)
    for (int i = t0; i < NN * 20; i += stride) {
        size_t o = (size_t)(i / 20) * LDK_BIG + 600 + 2 * (i % 20);
        *(uint32_t*)&g_AH[1][o] = 0u;
        *(uint32_t*)&g_AL[1][o] = 0u;
    }
    grid_barrier(PRE_CTAS);

    // ---- P2: node constants + per-block exclusive scan of indeg ----
    {
        __shared__ int sv[64];
        int base = blockIdx.x * PRE_CH;
        int idx = base + tid;
        int inb = (tid < PRE_CH && idx < NN);
        if (inb) {
            int d = g_deg[idx];
            g_dis[idx]  = (d > 0) ? (1.0f / sqrtf((float)d)) : 0.0f;
            g_diag[idx] = 2.0f / lmax[g_batch[idx]] - 1.0f;
        }
        int v = inb ? g_indeg[idx] : 0;
        int xv = v;
        // Hillis-Steele over 64 lanes (PRE_CH=55 <= 64); all 256 threads sync
        for (int off = 1; off < 64; off <<= 1) {
            if (tid < 64) sv[tid] = xv;
            __syncthreads();
            if (tid < 64 && tid >= off) xv += sv[tid - off];
            __syncthreads();
        }
        if (inb) g_rowptr[idx] = xv - v;     // exclusive, pre-offset
        if (tid < 64) sv[tid] = xv;
        __syncthreads();
        if (tid == 0) g_bsum[blockIdx.x] = sv[63];
    }
    grid_barrier(PRE_CTAS);

    // ---- P3: add block-prefix offsets ----
    {
        __shared__ int spart[256];
        int acc = 0;
        for (int j = tid; j < (int)blockIdx.x; j += 256) acc += g_bsum[j];
        spart[tid] = acc;
        __syncthreads();
        if (tid == 0) {
            int s = 0;
            for (int j = 0; j < 256; j++) s += spart[j];
            spart[0] = s;
        }
        __syncthreads();
        int off = spart[0];
        int idx = blockIdx.x * PRE_CH + tid;
        if (tid < PRE_CH && idx < NN) g_rowptr[idx] += off;
        if (t0 == 0) g_rowptr[NN] = EE;
    }
    grid_barrier(PRE_CTAS);

    // ---- P4: CSR fill with inline edge weight ----
    for (int e = t0; e < EE; e += stride) {
        int s = g_src[e], d = g_dstv[e];
        float w = -g_dis[s] * g_dis[d] * (2.0f / lmax[g_batch[s]]);
        int pos = g_rowptr[d] + atomicAdd(&g_cursor[d], 1);
        g_cw[pos] = make_int2(s, __float_as_int(w));
    }
}

// ------------------- fused prop pair (persistent + grid barrier) ------------
template <int F, int LD>
__device__ __forceinline__ void prop_phase(
        float* base, int srcS, float alpha, float beta, int useSub, int writeF32,
        __nv_bfloat16* __restrict__ Ah, __nv_bfloat16* __restrict__ Al,
        int aoff, int lda, int w, int lane) {
    const float* hs  = base + srcS * F;
    float*       out = base + (srcS + 1) * F;
    const float* sub = base;
    constexpr int NQ = F / 4;
    constexpr int NJ = (NQ + 31) / 32;
    float4 acc[NJ];
#pragma unroll
    for (int j = 0; j < NJ; j++) acc[j] = make_float4(0.f, 0.f, 0.f, 0.f);

    int e = g_rowptr[w], eend = g_rowptr[w + 1];
#pragma unroll 4
    for (; e < eend; e++) {
        int2 cw = __ldg(&g_cw[e]);
        float we = __int_as_float(cw.y);
        const float4* row = (const float4*)(hs + (size_t)cw.x * LD);
#pragma unroll
        for (int j = 0; j < NJ; j++) {
            int q = lane + 32 * j;
            if (q < NQ) {
                float4 r = __ldg(&row[q]);
                acc[j].x += we * r.x;
                acc[j].y += we * r.y;
                acc[j].z += we * r.z;
                acc[j].w += we * r.w;
            }
        }
    }
    float dg = g_diag[w];
    const float4* hrow = (const float4*)(hs  + (size_t)w * LD);
    float4*       orow = (float4*)      (out + (size_t)w * LD);
    const float4* srow = (const float4*)(sub + (size_t)w * LD);
    size_t abase = (size_t)w * lda + aoff;
#pragma unroll
    for (int j = 0; j < NJ; j++) {
        int q = lane + 32 * j;
        if (q < NQ) {
            float4 h4 = hrow[q];
            float4 v;
            v.x = alpha * (acc[j].x + dg * h4.x);
            v.y = alpha * (acc[j].y + dg * h4.y);
            v.z = alpha * (acc[j].z + dg * h4.z);
            v.w = alpha * (acc[j].w + dg * h4.w);
            if (useSub) {
                float4 s4 = srow[q];
                v.x += beta * s4.x; v.y += beta * s4.y;
                v.z += beta * s4.z; v.w += beta * s4.w;
            }
            if (writeF32) orow[q] = v;
            __nv_bfloat16 h0 = __float2bfloat16(v.x);
            __nv_bfloat16 h1 = __float2bfloat16(v.y);
            __nv_bfloat16 h2 = __float2bfloat16(v.z);
            __nv_bfloat16 h3 = __float2bfloat16(v.w);
            uint2 hp, lp;
            hp.x = (uint32_t)__bfloat16_as_ushort(h0) | ((uint32_t)__bfloat16_as_ushort(h1) << 16);
            hp.y = (uint32_t)__bfloat16_as_ushort(h2) | ((uint32_t)__bfloat16_as_ushort(h3) << 16);
            __nv_bfloat16 l0 = __float2bfloat16(v.x - __bfloat162float(h0));
            __nv_bfloat16 l1 = __float2bfloat16(v.y - __bfloat162float(h1));
            __nv_bfloat16 l2 = __float2bfloat16(v.z - __bfloat162float(h2));
            __nv_bfloat16 l3 = __float2bfloat16(v.w - __bfloat162float(h3));
            lp.x = (uint32_t)__bfloat16_as_ushort(l0) | ((uint32_t)__bfloat16_as_ushort(l1) << 16);
            lp.y = (uint32_t)__bfloat16_as_ushort(l2) | ((uint32_t)__bfloat16_as_ushort(l3) << 16);
            *(uint2*)(Ah + abase + 4 * q) = hp;
            *(uint2*)(Al + abase + 4 * q) = lp;
        }
    }
}

// pzh/pzl: optional A-buffer whose K-pad cols [600,640) are zeroed during
// phase 1 (used by the layer-2 prop to clear AH0/AL0 after the layer-1 GEMM
// finished consuming their LDK_S-layout contents).
template <int F, int LD>
__global__ __launch_bounds__(256, 6) void k_prop_fused(
        int sel, __nv_bfloat16* __restrict__ Ah, __nv_bfloat16* __restrict__ Al,
        int aoff1, int aoff2, int lda,
        __nv_bfloat16* __restrict__ pzh, __nv_bfloat16* __restrict__ pzl) {
    int lane = threadIdx.x & 31;
    int gwarp = blockIdx.x * 8 + (threadIdx.x >> 5);
    const int GW = PROP_CTAS * 8;
    float* base = g_T[sel];

    if (pzh) {
        int t0 = blockIdx.x * 256 + threadIdx.x;
        for (int i = t0; i < NN * 20; i += PROP_CTAS * 256) {
            size_t o = (size_t)(i / 20) * LDK_BIG + 600 + 2 * (i % 20);
            *(uint32_t*)&pzh[o] = 0u;
            *(uint32_t*)&pzl[o] = 0u;
        }
    }

    for (int w = gwarp; w < NN; w += GW)
        prop_phase<F, LD>(base, 0, 1.0f, 0.0f, 0, 1, Ah, Al, aoff1, lda, w, lane);

    grid_barrier(PROP_CTAS);

    for (int w = gwarp; w < NN; w += GW)
        prop_phase<F, LD>(base, 1, 2.0f, -1.0f, 1, 0, Ah, Al, aoff2, lda, w, lane);
}

// ---------------- all-layers W -> bf16 hi/lo (one launch) -------------------
__global__ void k_cvtB_all(const float* __restrict__ W1, const float* __restrict__ W2,
                           const float* __restrict__ W3, const float* __restrict__ W4) {
    int layer = blockIdx.z;
    const float* W = (layer == 0) ? W1 : (layer == 1) ? W2 : (layer == 2) ? W3 : W4;
    int LDK = layer ? LDK_BIG : LDK_S;
    int Kd  = layer ? 600 : 192;
    int k = blockIdx.x * 64 + threadIdx.x;
    int n = blockIdx.y;
    if (k >= LDK) return;
    float v = (n < HH && k < Kd) ? W[(size_t)k * HH + n] : 0.0f;
    __nv_bfloat16 h = __float2bfloat16(v);
    __nv_bfloat16 l = __float2bfloat16(v - __bfloat162float(h));
    size_t o = (size_t)n * LDK + k;
    g_B4h[layer][o] = h;
    g_B4l[layer][o] = l;
}

// ------------------------- HMMA GEMM (mma.sync bf16 3-split, fp32 acc) -----
#define SA_B   144
#define OA_H   0
#define OA_L   18432
#define OB_H   36864
#define OB_L   69120
#define STG    101376
#define SM_TOT (2 * STG)

__device__ __forceinline__ void ldsm_x4(uint32_t addr, uint32_t& r0, uint32_t& r1,
                                        uint32_t& r2, uint32_t& r3) {
    asm volatile("ldmatrix.sync.aligned.m8n8.x4.shared.b16 {%0,%1,%2,%3}, [%4];"
                 : "=r"(r0), "=r"(r1), "=r"(r2), "=r"(r3) : "r"(addr));
}
__device__ __forceinline__ void ldsm_x2(uint32_t addr, uint32_t& r0, uint32_t& r1) {
    asm volatile("ldmatrix.sync.aligned.m8n8.x2.shared.b16 {%0,%1}, [%2];"
                 : "=r"(r0), "=r"(r1) : "r"(addr));
}
__device__ __forceinline__ void mma16816(float* c, const uint32_t* a, const uint32_t* b) {
    asm volatile(
        "mma.sync.aligned.m16n8k16.row.col.f32.bf16.bf16.f32 "
        "{%0,%1,%2,%3}, {%4,%5,%6,%7}, {%8,%9}, {%0,%1,%2,%3};"
        : "+f"(c[0]), "+f"(c[1]), "+f"(c[2]), "+f"(c[3])
        : "r"(a[0]), "r"(a[1]), "r"(a[2]), "r"(a[3]), "r"(b[0]), "r"(b[1]));
}
__device__ __forceinline__ void cp16(uint32_t daddr, const void* saddr, uint32_t srcsz) {
    asm volatile("cp.async.cg.shared.global [%0], [%1], 16, %2;"
                 :: "r"(daddr), "l"(saddr), "r"(srcsz) : "memory");
}

__global__ __launch_bounds__(256, 1) void k_gemm_mma(
        const __nv_bfloat16* __restrict__ Ah, const __nv_bfloat16* __restrict__ Al,
        const __nv_bfloat16* __restrict__ Bh, const __nv_bfloat16* __restrict__ Bl,
        int LDK, int nch, const float* __restrict__ bias, int selC,
        __nv_bfloat16* __restrict__ nAh, __nv_bfloat16* __restrict__ nAl) {
    extern __shared__ char smdyn[];
    uint32_t sb = smem_to_u32(smdyn);
    int tid = threadIdx.x, lane = tid & 31, wid = tid >> 5;
    int warpM = wid >> 2, warpN = wid & 3;
    int mrow0 = warpM * 64;
    int ncol0 = warpN * 56;
    const int ldk8 = LDK >> 3;
    const int ntiles = (NN + 127) >> 7;   // 391

    const uint4* GAh = (const uint4*)Ah;
    const uint4* GAl = (const uint4*)Al;
    const uint4* GBh = (const uint4*)Bh;
    const uint4* GBl = (const uint4*)Bl;

    int rr = lane & 7;
    int aRow = rr + 8 * ((lane >> 3) & 1);
    int aK   = 8 * (lane >> 4);
    int bg   = lane >> 3;
    int bRow = rr + 8 * (bg >> 1);
    int bK   = 8 * (bg & 1);
    int bg2  = bg & 1;

    int lrow = tid >> 3, lcc = tid & 7;

    auto issue_stage = [&](int m0, int c, int s) {
        int k8 = c * 8;
        uint32_t sbase = sb + s * STG;
#pragma unroll
        for (int i = 0; i < 4; i++) {
            int row = lrow + 32 * i;
            int gm = m0 + row;
            int ok = (gm < NN);
            size_t gi = (size_t)(ok ? gm : 0) * ldk8 + k8 + lcc;
            uint32_t d = sbase + OA_H + row * SA_B + lcc * 16;
            cp16(d, GAh + gi, ok ? 16u : 0u);
            cp16(d + (OA_L - OA_H), GAl + gi, ok ? 16u : 0u);
        }
#pragma unroll
        for (int i = 0; i < 7; i++) {
            int row = lrow + 32 * i;
            size_t gi = (size_t)row * ldk8 + k8 + lcc;
            uint32_t d = sbase + OB_H + row * SA_B + lcc * 16;
            cp16(d, GBh + gi, 16u);
            cp16(d + (OB_L - OB_H), GBl + gi, 16u);
        }
        asm volatile("cp.async.commit_group;" ::: "memory");
    };

    int p = 0;
    if ((int)blockIdx.x < ntiles) issue_stage(blockIdx.x * 128, 0, 0);

    for (int t = blockIdx.x; t < ntiles; t += gridDim.x) {
        int m0 = t * 128;

        float acc[4][7][4];
#pragma unroll
        for (int i = 0; i < 4; i++)
#pragma unroll
            for (int j = 0; j < 7; j++)
#pragma unroll
                for (int q = 0; q < 4; q++) acc[i][j][q] = 0.0f;

        for (int c = 0; c < nch; c++) {
            asm volatile("cp.async.wait_group 0;" ::: "memory");
            __syncthreads();
            if (c + 1 < nch)
                issue_stage(m0, c + 1, p ^ 1);
            else if (t + (int)gridDim.x < ntiles)
                issue_stage((t + gridDim.x) * 128, 0, p ^ 1);

            uint32_t aH = sb + p * STG + OA_H;
            uint32_t aL = sb + p * STG + OA_L;
            uint32_t bH = sb + p * STG + OB_H;
            uint32_t bL = sb + p * STG + OB_L;

#pragma unroll
            for (int ks = 0; ks < 4; ks++) {
                int kel = ks * 16;
                uint32_t bh[7][2], bl[7][2];
#pragma unroll
                for (int q = 0; q < 3; q++) {
                    uint32_t boff = (uint32_t)((ncol0 + q * 16 + bRow) * SA_B + (kel + bK) * 2);
                    ldsm_x4(bH + boff, bh[2*q][0], bh[2*q][1], bh[2*q+1][0], bh[2*q+1][1]);
                    ldsm_x4(bL + boff, bl[2*q][0], bl[2*q][1], bl[2*q+1][0], bl[2*q+1][1]);
                }
                {
                    uint32_t boff = (uint32_t)((ncol0 + 48 + rr) * SA_B + (kel + 8 * bg2) * 2);
                    ldsm_x2(bH + boff, bh[6][0], bh[6][1]);
                    ldsm_x2(bL + boff, bl[6][0], bl[6][1]);
                }
#pragma unroll
                for (int mt = 0; mt < 4; mt++) {
                    uint32_t aoff = (uint32_t)((mrow0 + mt * 16 + aRow) * SA_B + (kel + aK) * 2);
                    uint32_t ah[4], al[4];
                    ldsm_x4(aH + aoff, ah[0], ah[1], ah[2], ah[3]);
                    ldsm_x4(aL + aoff, al[0], al[1], al[2], al[3]);
#pragma unroll
                    for (int nt = 0; nt < 7; nt++) {
                        mma16816(acc[mt][nt], ah, bh[nt]);
                        mma16816(acc[mt][nt], ah, bl[nt]);
                        mma16816(acc[mt][nt], al, bh[nt]);
                    }
                }
            }
            p ^= 1;
        }

        // epilogue: bias + relu; vectorized stores
        float* C = g_T[selC];
        int qrow = lane >> 2, qcol = (lane & 3) * 2;
#pragma unroll
        for (int mt = 0; mt < 4; mt++) {
            int row = m0 + mrow0 + mt * 16 + qrow;
#pragma unroll
            for (int nt = 0; nt < 7; nt++) {
                int col = ncol0 + nt * 8 + qcol;
                if (col < HH) {
                    float bz0 = __ldg(&bias[col]);
                    float bz1 = __ldg(&bias[col + 1]);
#pragma unroll
                    for (int half = 0; half < 2; half++) {
                        int r = row + 8 * half;
                        if (r < NN) {
                            float v0 = fmaxf(acc[mt][nt][2 * half]     + bz0, 0.0f);
                            float v1 = fmaxf(acc[mt][nt][2 * half + 1] + bz1, 0.0f);
                            *(float2*)(C + (size_t)r * 600 + col) = make_float2(v0, v1);
                            if (nAh) {
                                size_t ab = (size_t)r * LDK_BIG + col;
                                __nv_bfloat16 h0 = __float2bfloat16(v0);
                                __nv_bfloat16 h1 = __float2bfloat16(v1);
                                uint32_t hp = (uint32_t)__bfloat16_as_ushort(h0) |
                                              ((uint32_t)__bfloat16_as_ushort(h1) << 16);
                                __nv_bfloat16 l0 = __float2bfloat16(v0 - __bfloat162float(h0));
                                __nv_bfloat16 l1 = __float2bfloat16(v1 - __bfloat162float(h1));
                                uint32_t lp = (uint32_t)__bfloat16_as_ushort(l0) |
                                              ((uint32_t)__bfloat16_as_ushort(l1) << 16);
                                *(uint32_t*)(nAh + ab) = hp;
                                *(uint32_t*)(nAl + ab) = lp;
                            }
                        }
                    }
                }
            }
        }
    }
}

// ---------------- pooling + fc + log_softmax, fused per graph ---------------
__global__ void k_poolfc(const float* __restrict__ fw, const float* __restrict__ fb,
                         float* __restrict__ out) {
    __shared__ float4 ssum[4][52], smax[4][52];
    __shared__ float spool[400];
    int g = blockIdx.x;
    int q = threadIdx.x & 63, rg = threadIdx.x >> 6;
    int lo = 0, hi = NN;
    while (lo < hi) { int m = (lo + hi) >> 1; if (g_batch[m] < g) lo = m + 1; else hi = m; }
    int s = lo;
    lo = 0; hi = NN;
    while (lo < hi) { int m = (lo + hi) >> 1; if (g_batch[m] < g + 1) lo = m + 1; else hi = m; }
    int e = lo;

    float4 sum = make_float4(0.f, 0.f, 0.f, 0.f);
    float4 mx  = make_float4(-3.4e38f, -3.4e38f, -3.4e38f, -3.4e38f);
    if (q < 50) {
        for (int n = s + rg; n < e; n += 4) {
            const float4* row = (const float4*)(g_T[0] + (size_t)n * 600);
            float4 v = __ldg(&row[q]);
            sum.x += v.x; sum.y += v.y; sum.z += v.z; sum.w += v.w;
            mx.x = fmaxf(mx.x, v.x); mx.y = fmaxf(mx.y, v.y);
            mx.z = fmaxf(mx.z, v.z); mx.w = fmaxf(mx.w, v.w);
        }
        ssum[rg][q] = sum; smax[rg][q] = mx;
    }
    __syncthreads();
    if (rg == 0 && q < 50) {
#pragma unroll
        for (int r = 1; r < 4; r++) {
            float4 a = ssum[r][q], b = smax[r][q];
            sum.x += a.x; sum.y += a.y; sum.z += a.z; sum.w += a.w;
            mx.x = fmaxf(mx.x, b.x); mx.y = fmaxf(mx.y, b.y);
            mx.z = fmaxf(mx.z, b.z); mx.w = fmaxf(mx.w, b.w);
        }
        float c = fmaxf((float)(e - s), 1.0f);
        spool[4 * q]     = sum.x / c; spool[4 * q + 1] = sum.y / c;
        spool[4 * q + 2] = sum.z / c; spool[4 * q + 3] = sum.w / c;
        spool[HH + 4 * q]     = mx.x; spool[HH + 4 * q + 1] = mx.y;
        spool[HH + 4 * q + 2] = mx.z; spool[HH + 4 * q + 3] = mx.w;
    }
    __syncthreads();
    if (threadIdx.x < 32) {
        int lane = threadIdx.x;
        float z0 = 0.0f, z1 = 0.0f;
        for (int j = lane; j < 400; j += 32) {
            float v = spool[j];
            z0 += v * __ldg(&fw[2 * j]);
            z1 += v * __ldg(&fw[2 * j + 1]);
        }
#pragma unroll
        for (int off = 16; off > 0; off >>= 1) {
            z0 += __shfl_xor_sync(0xFFFFFFFF, z0, off);
            z1 += __shfl_xor_sync(0xFFFFFFFF, z1, off);
        }
        if (lane == 0) {
            z0 += fb[0]; z1 += fb[1];
            float m = fmaxf(z0, z1);
            float l = m + logf(expf(z0 - m) + expf(z1 - m));
            out[2 * g]     = z0 - l;
            out[2 * g + 1] = z1 - l;
        }
    }
}

// ------------------------- launch ------------------------------------------
extern "C" void kernel_launch(void* const* d_in, const int* in_sizes, int n_in,
                              void* d_out, int out_size) {
    const float* x     = (const float*)d_in[0];
    const void*  ei    = d_in[1];
    const void*  batch = d_in[2];
    const float* lmax  = (const float*)d_in[3];
    const float* W1 = (const float*)d_in[4];  const float* b1 = (const float*)d_in[5];
    const float* W2 = (const float*)d_in[6];  const float* b2 = (const float*)d_in[7];
    const float* W3 = (const float*)d_in[8];  const float* b3 = (const float*)d_in[9];
    const float* W4 = (const float*)d_in[10]; const float* b4 = (const float*)d_in[11];
    const float* fw = (const float*)d_in[12]; const float* fb = (const float*)d_in[13];
    float* out = (float*)d_out;

    cudaFuncSetAttribute(k_gemm_mma, cudaFuncAttributeMaxDynamicSharedMemorySize, SM_TOT);

    __nv_bfloat16 *AH0, *AL0, *AH1, *AL1, *BH, *BL;
    cudaGetSymbolAddress((void**)&AH0, g_AH);  AH1 = AH0 + (size_t)NN * LDK_BIG;
    cudaGetSymbolAddress((void**)&AL0, g_AL);  AL1 = AL0 + (size_t)NN * LDK_BIG;
    cudaGetSymbolAddress((void**)&BH, g_B4h);
    cudaGetSymbolAddress((void**)&BL, g_B4l);
    const size_t BSTR = (size_t)256 * LDK_BIG;

    // independent weight conversion first (off the critical chain)
    k_cvtB_all<<<dim3(10, 256, 4), 64>>>(W1, W2, W3, W4);

    // all graph preprocessing in one persistent kernel
    k_preproc<<<PRE_CTAS, 256>>>(ei, batch, x, lmax);

    // layer 1 (A buffers in LDK_S layout until consumed by GEMM below)
    k_prop_fused<64, 192><<<PROP_CTAS, 256>>>(0, AH0, AL0, 64, 128, LDK_S,
                                              nullptr, nullptr);
    k_gemm_mma<<<GEMM_GRID, 256, SM_TOT>>>(AH0, AL0, BH, BL, LDK_S, 3, b1, 1, AH1, AL1);

    // layer 2 (also zeroes AH0/AL0 K-pads — safe now that layer-1 GEMM is done)
    k_prop_fused<200, 600><<<PROP_CTAS, 256>>>(1, AH1, AL1, 200, 400, LDK_BIG,
                                               AH0, AL0);
    k_gemm_mma<<<GEMM_GRID, 256, SM_TOT>>>(AH1, AL1, BH + BSTR, BL + BSTR,
                                           LDK_BIG, 10, b2, 0, AH0, AL0);
    // layer 3
    k_prop_fused<200, 600><<<PROP_CTAS, 256>>>(0, AH0, AL0, 200, 400, LDK_BIG,
                                               nullptr, nullptr);
    k_gemm_mma<<<GEMM_GRID, 256, SM_TOT>>>(AH0, AL0, BH + 2 * BSTR, BL + 2 * BSTR,
                                           LDK_BIG, 10, b3, 1, AH1, AL1);
    // layer 4
    k_prop_fused<200, 600><<<PROP_CTAS, 256>>>(1, AH1, AL1, 200, 400, LDK_BIG,
                                               nullptr, nullptr);
    k_gemm_mma<<<GEMM_GRID, 256, SM_TOT>>>(AH1, AL1, BH + 3 * BSTR, BL + 3 * BSTR,
                                           LDK_BIG, 10, b4, 0, nullptr, nullptr);

    // pooling + fc + log_softmax (fused, one launch)
    k_poolfc<<<GG, 256>>>(fw, fb, out);
}